// round 3
// baseline (speedup 1.0000x reference)
#include <cuda_runtime.h>
#include <cuda_bf16.h>

// Problem constants (fixed shapes per reference)
#define Nn   100000
#define Ee   1600000
#define FIN  128
#define FHID 32
#define FOUT 2

// ---------------- scratch (__device__ globals; no allocation) ----------------
__device__ __align__(16) float g_g1[Nn * FHID];     // dinv-scaled h1        12.8 MB
__device__ __align__(16) float g_agg1[Nn * FHID];   // layer-1 scatter accum 12.8 MB
__device__ __align__(16) float g_g2[Nn * FOUT];     // dinv-scaled h2         0.8 MB
__device__ __align__(16) float g_agg2[Nn * FOUT];   // layer-2 scatter accum  0.8 MB
__device__ float g_deg[Nn];                          // degree (incl self loop)

// ---------------- kernels ----------------

// zero agg1/agg2, deg = 1 (self loop)
__global__ void k_init() {
    int t = blockIdx.x * blockDim.x + threadIdx.x;
    if (t < Nn * (FHID / 4)) {
        reinterpret_cast<float4*>(g_agg1)[t] = make_float4(0.f, 0.f, 0.f, 0.f);
    }
    if (t < Nn) {
        g_deg[t] = 1.0f;
        reinterpret_cast<float2*>(g_agg2)[t] = make_float2(0.f, 0.f);
    }
}

// in-degree count (edge_index is int32: [0:E]=row/source, [E:2E]=col/target)
__global__ void k_deg(const int* __restrict__ ei) {
    int e = blockIdx.x * blockDim.x + threadIdx.x;
    if (e >= Ee) return;
    int c = ei[Ee + e];
    atomicAdd(&g_deg[c], 1.0f);  // lowered to RED (return unused)
}

// g1 = dinv * (x @ W1)   — warp per node, 8 nodes per 256-thread block
__global__ void __launch_bounds__(256) k_gemm1(const float* __restrict__ x,
                                               const float* __restrict__ W1) {
    __shared__ float sW[FIN * FHID];   // 16 KB
    __shared__ float sx[8 * FIN];      //  4 KB
    int tid = threadIdx.x;
    for (int i = tid; i < FIN * FHID; i += 256) sW[i] = W1[i];

    int nodeBase = blockIdx.x * 8;
    {   // coalesced float4 load of 8 x-rows
        int idx = tid;                     // 0..255 float4s; 32 float4 per row
        int node = nodeBase + (idx >> 5);
        int off  = idx & 31;
        float4 v = make_float4(0.f, 0.f, 0.f, 0.f);
        if (node < Nn) v = reinterpret_cast<const float4*>(x)[(size_t)node * 32 + off];
        reinterpret_cast<float4*>(sx)[idx] = v;
    }
    __syncthreads();

    int w = tid >> 5, lane = tid & 31;
    int node = nodeBase + w;
    if (node >= Nn) return;
    const float* xr = &sx[w * FIN];
    float acc = 0.f;
#pragma unroll
    for (int k = 0; k < FIN; k++) acc = fmaf(xr[k], sW[k * FHID + lane], acc);
    float dinv = rsqrtf(g_deg[node]);
    g_g1[node * FHID + lane] = dinv * acc;
}

// layer-1 edge scatter: 8 lanes per edge, float4 gather + vector RED
__global__ void k_scatter1(const int* __restrict__ ei) {
    unsigned int t = blockIdx.x * blockDim.x + threadIdx.x;
    if (t >= (unsigned int)Ee * 8u) return;
    int e = t >> 3;
    int j = t & 7;
    int r = ei[e];
    int c = ei[Ee + e];
    float4 v = reinterpret_cast<const float4*>(g_g1)[r * (FHID / 4) + j];
    float4* dst = reinterpret_cast<float4*>(g_agg1) + c * (FHID / 4) + j;
    atomicAdd(dst, v);                 // RED.E.ADD.F32x4 (sm_90+, return unused)
}

// a1 = relu(dinv*(agg1 + g1) + b1); h2 = a1 @ W2; g2 = dinv * h2
__global__ void __launch_bounds__(256) k_layer2(const float* __restrict__ b1,
                                                const float* __restrict__ W2) {
    int w    = (blockIdx.x * blockDim.x + threadIdx.x) >> 5;
    int lane = threadIdx.x & 31;
    if (w >= Nn) return;
    float dinv = rsqrtf(g_deg[w]);
    float a = dinv * (g_agg1[w * FHID + lane] + g_g1[w * FHID + lane]) + b1[lane];
    a = fmaxf(a, 0.f);
    float p0 = a * W2[lane * 2 + 0];
    float p1 = a * W2[lane * 2 + 1];
#pragma unroll
    for (int o = 16; o > 0; o >>= 1) {
        p0 += __shfl_xor_sync(0xffffffffu, p0, o);
        p1 += __shfl_xor_sync(0xffffffffu, p1, o);
    }
    if (lane == 0) {
        reinterpret_cast<float2*>(g_g2)[w] = make_float2(dinv * p0, dinv * p1);
    }
}

// layer-2 edge scatter: 1 thread per edge, float2 gather + vector RED
__global__ void k_scatter2(const int* __restrict__ ei) {
    int e = blockIdx.x * blockDim.x + threadIdx.x;
    if (e >= Ee) return;
    int r = ei[e];
    int c = ei[Ee + e];
    float2 v = reinterpret_cast<const float2*>(g_g2)[r];
    float2* dst = reinterpret_cast<float2*>(g_agg2) + c;
    atomicAdd(dst, v);                 // RED.E.ADD.F32x2
}

// finalize: o = dinv*(agg2 + g2) + b2; log_softmax over 2 classes
__global__ void k_final(const float* __restrict__ b2, float* __restrict__ out) {
    int n = blockIdx.x * blockDim.x + threadIdx.x;
    if (n >= Nn) return;
    float dinv = rsqrtf(g_deg[n]);
    float2 s = reinterpret_cast<const float2*>(g_agg2)[n];
    float2 g = reinterpret_cast<const float2*>(g_g2)[n];
    float o0 = dinv * (s.x + g.x) + b2[0];
    float o1 = dinv * (s.y + g.y) + b2[1];
    float m = fmaxf(o0, o1);
    float lse = m + logf(expf(o0 - m) + expf(o1 - m));
    out[n * 2 + 0] = o0 - lse;
    out[n * 2 + 1] = o1 - lse;
}

// ---------------- launch ----------------
extern "C" void kernel_launch(void* const* d_in, const int* in_sizes, int n_in,
                              void* d_out, int out_size) {
    const float* x  = (const float*)d_in[0];
    const int*   ei = (const int*)d_in[1];   // int32 on the wire (JAX x64 disabled)
    const float* W1 = (const float*)d_in[2];
    const float* b1 = (const float*)d_in[3];
    const float* W2 = (const float*)d_in[4];
    const float* b2 = (const float*)d_in[5];
    float* out = (float*)d_out;

    const int T = 256;
    k_init    <<<(Nn * (FHID / 4) + T - 1) / T, T>>>();
    k_deg     <<<(Ee + T - 1) / T, T>>>(ei);
    k_gemm1   <<<(Nn + 7) / 8, T>>>(x, W1);
    k_scatter1<<<((unsigned)Ee * 8u + T - 1) / T, T>>>(ei);
    k_layer2  <<<(Nn * 32 + T - 1) / T, T>>>(b1, W2);
    k_scatter2<<<(Ee + T - 1) / T, T>>>(ei);
    k_final   <<<(Nn + T - 1) / T, T>>>(b2, out);
}